// round 9
// baseline (speedup 1.0000x reference)
#include <cuda_runtime.h>
#include <cuda_fp16.h>
#include <cstdint>

#define N_NODES 50000
#define D 128
#define E_EDGES 800000
#define M_TILE 128
#define N_TILES ((N_NODES + M_TILE - 1) / M_TILE)   // 391
#define PADK 40            // padded row: 40 fp16 = 80B (16B-aligned, conflict-free ldmatrix)
#define STAGE_BYTES 30720  // A(10240) + Bh(10240) + Bl(10240)
#define SMEM_BYTES (2 * STAGE_BYTES)

// ---------------- scratch globals (allocation forbidden) -------------------
__device__ __align__(16) float g_node[N_NODES * D];
__device__ __align__(16) float g_nbr [N_NODES * D];
__device__ __align__(16) float g_es  [N_NODES * D];
__device__ __align__(16) float g_deg [N_NODES];
__device__ int g_rowcnt [N_NODES];
__device__ int g_rowfill[N_NODES];
__device__ int g_rowptr [N_NODES + 1];
__device__ int g_csr    [E_EDGES];
__device__ __align__(16) __half g_Wn_h[D *     D];
__device__ __align__(16) __half g_Wn_l[D *     D];
__device__ __align__(16) __half g_We_h[D * 2 * D];
__device__ __align__(16) __half g_We_l[D * 2 * D];
__device__ __align__(16) __half g_Wu_h[D * 3 * D];
__device__ __align__(16) __half g_Wu_l[D * 3 * D];

// ---------------- helpers ---------------------------------------------------
__device__ __forceinline__ uint32_t smem_u32(const void* p) {
    uint32_t a;
    asm("{ .reg .u64 t; cvta.to.shared.u64 t, %1; cvt.u32.u64 %0, t; }"
        : "=r"(a) : "l"(p));
    return a;
}
__device__ __forceinline__ void sts128(uint32_t addr, uint4 v) {
    asm volatile("st.shared.v4.b32 [%0], {%1, %2, %3, %4};"
                 :: "r"(addr), "r"(v.x), "r"(v.y), "r"(v.z), "r"(v.w) : "memory");
}
__device__ __forceinline__ void ldsm_x4(uint32_t* r, uint32_t addr) {
    asm volatile("ldmatrix.sync.aligned.m8n8.x4.shared.b16 {%0, %1, %2, %3}, [%4];"
                 : "=r"(r[0]), "=r"(r[1]), "=r"(r[2]), "=r"(r[3]) : "r"(addr));
}
__device__ __forceinline__ void mma16816(float* d, const uint32_t* a, const uint32_t* b) {
    asm volatile(
        "mma.sync.aligned.m16n8k16.row.col.f32.f16.f16.f32 "
        "{%0, %1, %2, %3}, {%4, %5, %6, %7}, {%8, %9}, {%0, %1, %2, %3};"
        : "+f"(d[0]), "+f"(d[1]), "+f"(d[2]), "+f"(d[3])
        : "r"(a[0]), "r"(a[1]), "r"(a[2]), "r"(a[3]), "r"(b[0]), "r"(b[1]));
}
__device__ __forceinline__ uint32_t pack_h2(float a, float b) {
    __half2 h = __floats2half2_rn(a, b);
    return *reinterpret_cast<uint32_t*>(&h);
}
__device__ __forceinline__ float gelu_exact(float u) {
    return 0.5f * u * (1.0f + erff(u * 0.70710678118654752f));
}

// ---------------------------------------------------------------------------
__global__ void zero_cnt_kernel() {
    int i = blockIdx.x * blockDim.x + threadIdx.x;
    if (i < N_NODES) { g_rowcnt[i] = 0; g_rowfill[i] = 0; }
}

// Split weights to fp16 hi/lo; layout stays [n][K] (K-major = mma ".col" B).
__global__ void prep_weights(const float* __restrict__ Wn,
                             const float* __restrict__ We,
                             const float* __restrict__ Wu) {
    int i = blockIdx.x * blockDim.x + threadIdx.x;
    if (i < D * D) {
        float w = Wn[i];
        __half h = __float2half_rn(w);
        g_Wn_h[i] = h; g_Wn_l[i] = __float2half_rn(w - __half2float(h));
    }
    if (i < 2 * D * D) {
        float w = We[i];
        __half h = __float2half_rn(w);
        g_We_h[i] = h; g_We_l[i] = __float2half_rn(w - __half2float(h));
    }
    if (i < 3 * D * D) {
        float w = Wu[i];
        __half h = __float2half_rn(w);
        g_Wu_h[i] = h; g_Wu_l[i] = __float2half_rn(w - __half2float(h));
    }
}

// ---------------- CSR build --------------------------------------------------
__global__ void count_kernel(const int* __restrict__ ei) {
    int e = blockIdx.x * blockDim.x + threadIdx.x;
    if (e < E_EDGES) atomicAdd(&g_rowcnt[ei[e]], 1);
}

// Single-block exclusive prefix scan over 50k counts; also emits g_deg.
#define SCAN_T 1024
__global__ void __launch_bounds__(SCAN_T) scan_kernel() {
    __shared__ int s[SCAN_T];
    int t = threadIdx.x;
    const int CH = (N_NODES + SCAN_T - 1) / SCAN_T;   // 49
    int beg = t * CH, end = min(beg + CH, N_NODES);
    int sum = 0;
    for (int i = beg; i < end; i++) sum += g_rowcnt[i];
    s[t] = sum;
    __syncthreads();
    for (int off = 1; off < SCAN_T; off <<= 1) {
        int v = (t >= off) ? s[t - off] : 0;
        __syncthreads();
        s[t] += v;
        __syncthreads();
    }
    int run = (t == 0) ? 0 : s[t - 1];
    for (int i = beg; i < end; i++) {
        g_rowptr[i] = run;
        int c = g_rowcnt[i];
        g_deg[i] = (float)c;
        run += c;
    }
    if (t == SCAN_T - 1) g_rowptr[N_NODES] = run;
}

__global__ void fill_kernel(const int* __restrict__ ei) {
    int e = blockIdx.x * blockDim.x + threadIdx.x;
    if (e >= E_EDGES) return;
    int s = ei[e];
    int pos = atomicAdd(&g_rowfill[s], 1);
    g_csr[g_rowptr[s] + pos] = ei[E_EDGES + e];
}

// Gather: one warp per node; nbr[v] = sum over csr row of node[dst].
__global__ void __launch_bounds__(256) gather_kernel() {
    int node = (blockIdx.x * blockDim.x + threadIdx.x) >> 5;
    if (node >= N_NODES) return;
    int lane = threadIdx.x & 31;
    int i   = g_rowptr[node];
    int end = g_rowptr[node + 1];
    float4 acc = make_float4(0.f, 0.f, 0.f, 0.f);
    for (; i + 4 <= end; i += 4) {
        int d0 = g_csr[i], d1 = g_csr[i + 1], d2 = g_csr[i + 2], d3 = g_csr[i + 3];
        float4 v0 = ((const float4*)(g_node + (size_t)d0 * D))[lane];
        float4 v1 = ((const float4*)(g_node + (size_t)d1 * D))[lane];
        float4 v2 = ((const float4*)(g_node + (size_t)d2 * D))[lane];
        float4 v3 = ((const float4*)(g_node + (size_t)d3 * D))[lane];
        acc.x += v0.x + v1.x + v2.x + v3.x;
        acc.y += v0.y + v1.y + v2.y + v3.y;
        acc.z += v0.z + v1.z + v2.z + v3.z;
        acc.w += v0.w + v1.w + v2.w + v3.w;
    }
    for (; i < end; i++) {
        int dd = g_csr[i];
        float4 v = ((const float4*)(g_node + (size_t)dd * D))[lane];
        acc.x += v.x; acc.y += v.y; acc.z += v.z; acc.w += v.w;
    }
    ((float4*)(g_nbr + (size_t)node * D))[lane] = acc;
}

// ---------------------------------------------------------------------------
// fp16 HMMA GEMM (A single fp16, B split hi/lo), double-buffered smem:
//   C[M x 128] = A[M x K] @ W[128][K]^T + bias,  C = A*Bh + A*Bl
// MODE 0: A = x,                        W = Wn, C = g_node, bias = bn
// MODE 1: A = [deg*node | nbr],         W = We, C = g_es,   bias = deg*be
// MODE 2: A = gelu([node | nbr | es]),  W = Wu, C = d_out,  bias = bu
// CTA: 128x128 tile, 256 threads, 8 warps (4x2), warp tile 32x64, BK=32.
template <int MODE, int K>
__global__ void __launch_bounds__(256) mma_gemm(const float* __restrict__ A0,
                                                const float* __restrict__ bias,
                                                float* __restrict__ Cout) {
    extern __shared__ __align__(16) char dynsmem[];
    const uint32_t sbase = smem_u32(dynsmem);

    const int tid  = threadIdx.x;
    const int lane = tid & 31;
    const int wid  = tid >> 5;
    const int wm   = wid >> 1;          // 0..3  (M)
    const int wn   = wid & 1;           // 0..1  (N)
    const int blockRow = blockIdx.x * M_TILE;

    const __half* WH = (MODE == 0) ? g_Wn_h : (MODE == 1) ? g_We_h : g_Wu_h;
    const __half* WL = (MODE == 0) ? g_Wn_l : (MODE == 1) ? g_We_l : g_Wu_l;

    // ---- per-thread load duty: A row = tid/2, B row n = tid/2, half = tid&1
    const int ldRow = tid >> 1;
    const int half  = tid & 1;
    const int mA    = blockRow + ldRow;
    const bool mvA  = (mA < N_NODES);
    const float degA = (MODE == 1) ? (mvA ? g_deg[mA] : 0.f) : 1.f;

    constexpr int NC = K / 32;

    float d[2][8][4];
#pragma unroll
    for (int i = 0; i < 2; i++)
#pragma unroll
        for (int j = 0; j < 8; j++)
#pragma unroll
            for (int q = 0; q < 4; q++) d[i][j][q] = 0.f;

    float4 aReg[4];
    uint4  bRegH[2], bRegL[2];

    auto loadChunk = [&](int c) {
        const float* srcp;
        if (MODE == 0) {
            srcp = A0 + (size_t)mA * D + c * 32;
        } else if (MODE == 1) {
            srcp = (c < 4) ? g_node + (size_t)mA * D + c * 32
                           : g_nbr  + (size_t)mA * D + (c - 4) * 32;
        } else {
            int seg = c >> 2;
            const float* b = (seg == 0) ? g_node : (seg == 1) ? g_nbr : g_es;
            srcp = b + (size_t)mA * D + (c & 3) * 32;
        }
        const float4* p4 = (const float4*)(srcp + half * 16);
        if (mvA) {
#pragma unroll
            for (int q = 0; q < 4; q++) aReg[q] = p4[q];
        } else {
            float4 z = make_float4(0.f, 0.f, 0.f, 0.f);
#pragma unroll
            for (int q = 0; q < 4; q++) aReg[q] = z;
        }
        const uint4* ph = (const uint4*)(WH + (size_t)ldRow * K + c * 32 + half * 16);
        const uint4* pl = (const uint4*)(WL + (size_t)ldRow * K + c * 32 + half * 16);
        bRegH[0] = ph[0]; bRegH[1] = ph[1];
        bRegL[0] = pl[0]; bRegL[1] = pl[1];
    };

    auto storeChunk = [&](int c, uint32_t stage) {
        uint32_t aA  = stage;
        uint32_t aBh = stage + 10240;
        uint32_t aBl = stage + 20480;
        float scale = 1.f;
        if (MODE == 1) scale = (c < 4) ? degA : 1.f;
        uint4 H[2];
#pragma unroll
        for (int q = 0; q < 2; q++) {
            float4 fa = aReg[2 * q], fb = aReg[2 * q + 1];
            if (MODE == 1) {
                fa.x *= scale; fa.y *= scale; fa.z *= scale; fa.w *= scale;
                fb.x *= scale; fb.y *= scale; fb.z *= scale; fb.w *= scale;
            }
            if (MODE == 2) {
                fa.x = gelu_exact(fa.x); fa.y = gelu_exact(fa.y);
                fa.z = gelu_exact(fa.z); fa.w = gelu_exact(fa.w);
                fb.x = gelu_exact(fb.x); fb.y = gelu_exact(fb.y);
                fb.z = gelu_exact(fb.z); fb.w = gelu_exact(fb.w);
            }
            H[q].x = pack_h2(fa.x, fa.y);
            H[q].y = pack_h2(fa.z, fa.w);
            H[q].z = pack_h2(fb.x, fb.y);
            H[q].w = pack_h2(fb.z, fb.w);
        }
        uint32_t off = (uint32_t)ldRow * 80u + half * 32u;
        sts128(aA + off,       H[0]);
        sts128(aA + off + 16,  H[1]);
        sts128(aBh + off,      bRegH[0]);
        sts128(aBh + off + 16, bRegH[1]);
        sts128(aBl + off,      bRegL[0]);
        sts128(aBl + off + 16, bRegL[1]);
    };

    // ---- prologue ----
    loadChunk(0);
    storeChunk(0, sbase);
    __syncthreads();

    for (int c = 0; c < NC; c++) {
        const uint32_t cur = sbase + (uint32_t)(c & 1) * STAGE_BYTES;
        if (c + 1 < NC) loadChunk(c + 1);   // global prefetch into regs

        const uint32_t aA  = cur;
        const uint32_t aBh = cur + 10240;
        const uint32_t aBl = cur + 20480;
#pragma unroll
        for (int ks = 0; ks < 2; ks++) {
            // A fragments, 2 m-tiles
            uint32_t ah[2][4];
            {
                uint32_t kb = (uint32_t)(ks * 16 + ((lane >> 4) << 3)) * 2u;
#pragma unroll
                for (int i = 0; i < 2; i++) {
                    uint32_t r = (uint32_t)(wm * 32 + i * 16 + (lane & 15));
                    ldsm_x4(ah[i], aA + r * 80u + kb);
                }
            }
            // B fragments (hi & lo), 8 n-tiles via 4 non-trans x4 loads
            uint32_t bh[16], bl[16];
            {
                uint32_t kb = (uint32_t)(ks * 16 + (lane & 8)) * 2u;
#pragma unroll
                for (int j = 0; j < 4; j++) {
                    uint32_t r = (uint32_t)(wn * 64 + j * 16 + (lane & 7) + ((lane & 16) ? 8 : 0));
                    uint32_t off = r * 80u + kb;
                    ldsm_x4(bh + j * 4, aBh + off);
                    ldsm_x4(bl + j * 4, aBl + off);
                }
            }
#pragma unroll
            for (int i = 0; i < 2; i++) {
#pragma unroll
                for (int j = 0; j < 8; j++) {
                    int bi = (j >> 1) * 4 + (j & 1) * 2;
                    mma16816(d[i][j], ah[i], bh + bi);
                    mma16816(d[i][j], ah[i], bl + bi);
                }
            }
        }

        if (c + 1 < NC)
            storeChunk(c + 1, sbase + (uint32_t)((c + 1) & 1) * STAGE_BYTES);
        __syncthreads();
    }

    // ---- epilogue ----
    float* Cbase = (MODE == 0) ? g_node : (MODE == 1) ? g_es : Cout;
#pragma unroll
    for (int i = 0; i < 2; i++) {
        int r0 = blockRow + wm * 32 + i * 16 + (lane >> 2);
        int r1 = r0 + 8;
        bool v0 = r0 < N_NODES, v1 = r1 < N_NODES;
        float s0 = 1.f, s1 = 1.f;
        if (MODE == 1) {
            s0 = v0 ? g_deg[r0] : 0.f;
            s1 = v1 ? g_deg[r1] : 0.f;
        }
        float* c0 = Cbase + (size_t)r0 * D;
        float* c1 = Cbase + (size_t)r1 * D;
#pragma unroll
        for (int j = 0; j < 8; j++) {
            int col = wn * 64 + j * 8 + (lane & 3) * 2;
            float b0 = bias[col], b1 = bias[col + 1];
            if (v0) {
                float2 o = make_float2(d[i][j][0] + s0 * b0, d[i][j][1] + s0 * b1);
                *(float2*)(c0 + col) = o;
            }
            if (v1) {
                float2 o = make_float2(d[i][j][2] + s1 * b0, d[i][j][3] + s1 * b1);
                *(float2*)(c1 + col) = o;
            }
        }
    }
}

// ---------------------------------------------------------------------------
extern "C" void kernel_launch(void* const* d_in, const int* in_sizes, int n_in,
                              void* d_out, int out_size) {
    const float* x  = (const float*)d_in[0];
    const int*   ei = (const int*)d_in[1];
    const float* Wn = (const float*)d_in[2];
    const float* bn = (const float*)d_in[3];
    const float* We = (const float*)d_in[4];
    const float* be = (const float*)d_in[5];
    const float* Wu = (const float*)d_in[6];
    const float* bu = (const float*)d_in[7];
    float* out = (float*)d_out;
    (void)in_sizes; (void)n_in; (void)out_size;

    static bool attr_done = false;
    if (!attr_done) {
        cudaFuncSetAttribute(mma_gemm<0, 128>, cudaFuncAttributeMaxDynamicSharedMemorySize, SMEM_BYTES);
        cudaFuncSetAttribute(mma_gemm<1, 256>, cudaFuncAttributeMaxDynamicSharedMemorySize, SMEM_BYTES);
        cudaFuncSetAttribute(mma_gemm<2, 384>, cudaFuncAttributeMaxDynamicSharedMemorySize, SMEM_BYTES);
        attr_done = true;
    }

    const int egrid = (E_EDGES + 255) / 256;

    // CSR build (independent of GEMM-1; deg needed before GEMM-2)
    zero_cnt_kernel<<<(N_NODES + 255) / 256, 256>>>();
    prep_weights<<<(3 * D * D + 255) / 256, 256>>>(Wn, We, Wu);
    count_kernel<<<egrid, 256>>>(ei);
    scan_kernel<<<1, SCAN_T>>>();
    fill_kernel<<<egrid, 256>>>(ei);

    // 1. node = x @ Wn^T + bn
    mma_gemm<0, 128><<<N_TILES, 256, SMEM_BYTES>>>(x, bn, nullptr);

    // 2. nbr_sum via CSR gather (warp per node)
    gather_kernel<<<(N_NODES * 32 + 255) / 256, 256>>>();

    // 3. edge_sum = [deg*node | nbr] @ We^T + deg*be
    mma_gemm<1, 256><<<N_TILES, 256, SMEM_BYTES>>>(nullptr, be, nullptr);

    // 4. out = gelu([node | nbr | edge_sum]) @ Wu^T + bu
    mma_gemm<2, 384><<<N_TILES, 256, SMEM_BYTES>>>(nullptr, bu, out);
}

// round 10
// speedup vs baseline: 1.3901x; 1.3901x over previous
#include <cuda_runtime.h>
#include <cuda_fp16.h>
#include <cstdint>

#define N_NODES 50000
#define D 128
#define E_EDGES 800000
#define M_TILE 128
#define N_TILES ((N_NODES + M_TILE - 1) / M_TILE)   // 391
#define PADK 40            // padded row: 40 fp16 = 80B (16B-aligned, conflict-free ldmatrix)
#define STAGE_BYTES 30720  // A(10240) + Bh(10240) + Bl(10240)
#define SMEM_BYTES (2 * STAGE_BYTES)
#define SCB 1024
#define NSCB ((N_NODES + SCB - 1) / SCB)            // 49

// ---------------- scratch globals (allocation forbidden) -------------------
__device__ __align__(16) float g_node[N_NODES * D];
__device__ __align__(16) float g_nbr [N_NODES * D];
__device__ __align__(16) float g_es  [N_NODES * D];
__device__ __align__(16) float g_deg [N_NODES];
__device__ int g_rowcnt [N_NODES];
__device__ int g_rowfill[N_NODES];
__device__ int g_rowptr [N_NODES + 1];
__device__ int g_csr    [E_EDGES];
__device__ int g_bsum   [NSCB];
__device__ __align__(16) __half g_Wn_h[D *     D];
__device__ __align__(16) __half g_Wn_l[D *     D];
__device__ __align__(16) __half g_We_h[D * 2 * D];
__device__ __align__(16) __half g_We_l[D * 2 * D];
__device__ __align__(16) __half g_Wu_h[D * 3 * D];
__device__ __align__(16) __half g_Wu_l[D * 3 * D];

// ---------------- helpers ---------------------------------------------------
__device__ __forceinline__ uint32_t smem_u32(const void* p) {
    uint32_t a;
    asm("{ .reg .u64 t; cvta.to.shared.u64 t, %1; cvt.u32.u64 %0, t; }"
        : "=r"(a) : "l"(p));
    return a;
}
__device__ __forceinline__ void sts128(uint32_t addr, uint4 v) {
    asm volatile("st.shared.v4.b32 [%0], {%1, %2, %3, %4};"
                 :: "r"(addr), "r"(v.x), "r"(v.y), "r"(v.z), "r"(v.w) : "memory");
}
__device__ __forceinline__ void ldsm_x4(uint32_t* r, uint32_t addr) {
    asm volatile("ldmatrix.sync.aligned.m8n8.x4.shared.b16 {%0, %1, %2, %3}, [%4];"
                 : "=r"(r[0]), "=r"(r[1]), "=r"(r[2]), "=r"(r[3]) : "r"(addr));
}
__device__ __forceinline__ void mma16816(float* d, const uint32_t* a, const uint32_t* b) {
    asm volatile(
        "mma.sync.aligned.m16n8k16.row.col.f32.f16.f16.f32 "
        "{%0, %1, %2, %3}, {%4, %5, %6, %7}, {%8, %9}, {%0, %1, %2, %3};"
        : "+f"(d[0]), "+f"(d[1]), "+f"(d[2]), "+f"(d[3])
        : "r"(a[0]), "r"(a[1]), "r"(a[2]), "r"(a[3]), "r"(b[0]), "r"(b[1]));
}
__device__ __forceinline__ uint32_t pack_h2(float a, float b) {
    __half2 h = __floats2half2_rn(a, b);
    return *reinterpret_cast<uint32_t*>(&h);
}
__device__ __forceinline__ float gelu_exact(float u) {
    return 0.5f * u * (1.0f + erff(u * 0.70710678118654752f));
}

// ---------------------------------------------------------------------------
__global__ void zero_cnt_kernel() {
    int i = blockIdx.x * blockDim.x + threadIdx.x;
    if (i < N_NODES) { g_rowcnt[i] = 0; g_rowfill[i] = 0; }
}

// Split weights to fp16 hi/lo; layout stays [n][K] (K-major = mma ".col" B).
__global__ void prep_weights(const float* __restrict__ Wn,
                             const float* __restrict__ We,
                             const float* __restrict__ Wu) {
    int i = blockIdx.x * blockDim.x + threadIdx.x;
    if (i < D * D) {
        float w = Wn[i];
        __half h = __float2half_rn(w);
        g_Wn_h[i] = h; g_Wn_l[i] = __float2half_rn(w - __half2float(h));
    }
    if (i < 2 * D * D) {
        float w = We[i];
        __half h = __float2half_rn(w);
        g_We_h[i] = h; g_We_l[i] = __float2half_rn(w - __half2float(h));
    }
    if (i < 3 * D * D) {
        float w = Wu[i];
        __half h = __float2half_rn(w);
        g_Wu_h[i] = h; g_Wu_l[i] = __float2half_rn(w - __half2float(h));
    }
}

// ---------------- CSR build --------------------------------------------------
__global__ void count_kernel(const int* __restrict__ ei) {
    int e = blockIdx.x * blockDim.x + threadIdx.x;
    if (e < E_EDGES) atomicAdd(&g_rowcnt[ei[e]], 1);
}

// Phase 1: per-block Hillis-Steele scan (1024 nodes/block). Writes the
// block-local EXCLUSIVE scan into g_rowptr, the block total into g_bsum,
// and g_deg.
__global__ void __launch_bounds__(SCB) scan1_kernel() {
    __shared__ int s[SCB];
    int t = threadIdx.x;
    int i = blockIdx.x * SCB + t;
    int c = (i < N_NODES) ? g_rowcnt[i] : 0;
    s[t] = c;
    __syncthreads();
#pragma unroll
    for (int off = 1; off < SCB; off <<= 1) {
        int v = (t >= off) ? s[t - off] : 0;
        __syncthreads();
        s[t] += v;
        __syncthreads();
    }
    if (i < N_NODES) {
        g_rowptr[i] = s[t] - c;        // exclusive within block
        g_deg[i] = (float)c;
    }
    if (t == SCB - 1) g_bsum[blockIdx.x] = s[t];
}

// Phase 2: serial scan of the 49 block totals (single thread: trivial work).
__global__ void scan2_kernel() {
    if (threadIdx.x == 0) {
        int run = 0;
        for (int b = 0; b < NSCB; b++) {
            int v = g_bsum[b];
            g_bsum[b] = run;
            run += v;
        }
        g_rowptr[N_NODES] = run;       // == E_EDGES
    }
}

// Phase 3: add block offsets.
__global__ void __launch_bounds__(SCB) scan3_kernel() {
    int i = blockIdx.x * SCB + threadIdx.x;
    if (i < N_NODES && blockIdx.x > 0) g_rowptr[i] += g_bsum[blockIdx.x];
}

__global__ void fill_kernel(const int* __restrict__ ei) {
    int e = blockIdx.x * blockDim.x + threadIdx.x;
    if (e >= E_EDGES) return;
    int s = ei[e];
    int pos = atomicAdd(&g_rowfill[s], 1);
    g_csr[g_rowptr[s] + pos] = ei[E_EDGES + e];
}

// Gather: one warp per node; nbr[v] = sum over csr row of node[dst].
__global__ void __launch_bounds__(256) gather_kernel() {
    int node = (blockIdx.x * blockDim.x + threadIdx.x) >> 5;
    if (node >= N_NODES) return;
    int lane = threadIdx.x & 31;
    int i   = g_rowptr[node];
    int end = g_rowptr[node + 1];
    float4 acc = make_float4(0.f, 0.f, 0.f, 0.f);
    for (; i + 4 <= end; i += 4) {
        int d0 = g_csr[i], d1 = g_csr[i + 1], d2 = g_csr[i + 2], d3 = g_csr[i + 3];
        float4 v0 = ((const float4*)(g_node + (size_t)d0 * D))[lane];
        float4 v1 = ((const float4*)(g_node + (size_t)d1 * D))[lane];
        float4 v2 = ((const float4*)(g_node + (size_t)d2 * D))[lane];
        float4 v3 = ((const float4*)(g_node + (size_t)d3 * D))[lane];
        acc.x += v0.x + v1.x + v2.x + v3.x;
        acc.y += v0.y + v1.y + v2.y + v3.y;
        acc.z += v0.z + v1.z + v2.z + v3.z;
        acc.w += v0.w + v1.w + v2.w + v3.w;
    }
    for (; i < end; i++) {
        int dd = g_csr[i];
        float4 v = ((const float4*)(g_node + (size_t)dd * D))[lane];
        acc.x += v.x; acc.y += v.y; acc.z += v.z; acc.w += v.w;
    }
    ((float4*)(g_nbr + (size_t)node * D))[lane] = acc;
}

// ---------------------------------------------------------------------------
// fp16 HMMA GEMM (A single fp16, B split hi/lo), double-buffered smem:
//   C[M x 128] = A[M x K] @ W[128][K]^T + bias,  C = A*Bh + A*Bl
// MODE 0: A = x,                        W = Wn, C = g_node, bias = bn
// MODE 1: A = [deg*node | nbr],         W = We, C = g_es,   bias = deg*be
// MODE 2: A = gelu([node | nbr | es]),  W = Wu, C = d_out,  bias = bu
// CTA: 128x128 tile, 256 threads, 8 warps (4x2), warp tile 32x64, BK=32.
template <int MODE, int K>
__global__ void __launch_bounds__(256) mma_gemm(const float* __restrict__ A0,
                                                const float* __restrict__ bias,
                                                float* __restrict__ Cout) {
    extern __shared__ __align__(16) char dynsmem[];
    const uint32_t sbase = smem_u32(dynsmem);

    const int tid  = threadIdx.x;
    const int lane = tid & 31;
    const int wid  = tid >> 5;
    const int wm   = wid >> 1;          // 0..3  (M)
    const int wn   = wid & 1;           // 0..1  (N)
    const int blockRow = blockIdx.x * M_TILE;

    const __half* WH = (MODE == 0) ? g_Wn_h : (MODE == 1) ? g_We_h : g_Wu_h;
    const __half* WL = (MODE == 0) ? g_Wn_l : (MODE == 1) ? g_We_l : g_Wu_l;

    // ---- per-thread load duty: A row = tid/2, B row n = tid/2, half = tid&1
    const int ldRow = tid >> 1;
    const int half  = tid & 1;
    const int mA    = blockRow + ldRow;
    const bool mvA  = (mA < N_NODES);
    const float degA = (MODE == 1) ? (mvA ? g_deg[mA] : 0.f) : 1.f;

    constexpr int NC = K / 32;

    float d[2][8][4];
#pragma unroll
    for (int i = 0; i < 2; i++)
#pragma unroll
        for (int j = 0; j < 8; j++)
#pragma unroll
            for (int q = 0; q < 4; q++) d[i][j][q] = 0.f;

    float4 aReg[4];
    uint4  bRegH[2], bRegL[2];

    auto loadChunk = [&](int c) {
        const float* srcp;
        if (MODE == 0) {
            srcp = A0 + (size_t)mA * D + c * 32;
        } else if (MODE == 1) {
            srcp = (c < 4) ? g_node + (size_t)mA * D + c * 32
                           : g_nbr  + (size_t)mA * D + (c - 4) * 32;
        } else {
            int seg = c >> 2;
            const float* b = (seg == 0) ? g_node : (seg == 1) ? g_nbr : g_es;
            srcp = b + (size_t)mA * D + (c & 3) * 32;
        }
        const float4* p4 = (const float4*)(srcp + half * 16);
        if (mvA) {
#pragma unroll
            for (int q = 0; q < 4; q++) aReg[q] = p4[q];
        } else {
            float4 z = make_float4(0.f, 0.f, 0.f, 0.f);
#pragma unroll
            for (int q = 0; q < 4; q++) aReg[q] = z;
        }
        const uint4* ph = (const uint4*)(WH + (size_t)ldRow * K + c * 32 + half * 16);
        const uint4* pl = (const uint4*)(WL + (size_t)ldRow * K + c * 32 + half * 16);
        bRegH[0] = ph[0]; bRegH[1] = ph[1];
        bRegL[0] = pl[0]; bRegL[1] = pl[1];
    };

    auto storeChunk = [&](int c, uint32_t stage) {
        uint32_t aA  = stage;
        uint32_t aBh = stage + 10240;
        uint32_t aBl = stage + 20480;
        float scale = 1.f;
        if (MODE == 1) scale = (c < 4) ? degA : 1.f;
        uint4 H[2];
#pragma unroll
        for (int q = 0; q < 2; q++) {
            float4 fa = aReg[2 * q], fb = aReg[2 * q + 1];
            if (MODE == 1) {
                fa.x *= scale; fa.y *= scale; fa.z *= scale; fa.w *= scale;
                fb.x *= scale; fb.y *= scale; fb.z *= scale; fb.w *= scale;
            }
            if (MODE == 2) {
                fa.x = gelu_exact(fa.x); fa.y = gelu_exact(fa.y);
                fa.z = gelu_exact(fa.z); fa.w = gelu_exact(fa.w);
                fb.x = gelu_exact(fb.x); fb.y = gelu_exact(fb.y);
                fb.z = gelu_exact(fb.z); fb.w = gelu_exact(fb.w);
            }
            H[q].x = pack_h2(fa.x, fa.y);
            H[q].y = pack_h2(fa.z, fa.w);
            H[q].z = pack_h2(fb.x, fb.y);
            H[q].w = pack_h2(fb.z, fb.w);
        }
        uint32_t off = (uint32_t)ldRow * 80u + half * 32u;
        sts128(aA + off,       H[0]);
        sts128(aA + off + 16,  H[1]);
        sts128(aBh + off,      bRegH[0]);
        sts128(aBh + off + 16, bRegH[1]);
        sts128(aBl + off,      bRegL[0]);
        sts128(aBl + off + 16, bRegL[1]);
    };

    // ---- prologue ----
    loadChunk(0);
    storeChunk(0, sbase);
    __syncthreads();

    for (int c = 0; c < NC; c++) {
        const uint32_t cur = sbase + (uint32_t)(c & 1) * STAGE_BYTES;
        if (c + 1 < NC) loadChunk(c + 1);   // global prefetch into regs

        const uint32_t aA  = cur;
        const uint32_t aBh = cur + 10240;
        const uint32_t aBl = cur + 20480;
#pragma unroll
        for (int ks = 0; ks < 2; ks++) {
            // A fragments, 2 m-tiles
            uint32_t ah[2][4];
            {
                uint32_t kb = (uint32_t)(ks * 16 + ((lane >> 4) << 3)) * 2u;
#pragma unroll
                for (int i = 0; i < 2; i++) {
                    uint32_t r = (uint32_t)(wm * 32 + i * 16 + (lane & 15));
                    ldsm_x4(ah[i], aA + r * 80u + kb);
                }
            }
            // B fragments (hi & lo), 8 n-tiles via 4 non-trans x4 loads
            uint32_t bh[16], bl[16];
            {
                uint32_t kb = (uint32_t)(ks * 16 + (lane & 8)) * 2u;
#pragma unroll
                for (int j = 0; j < 4; j++) {
                    uint32_t r = (uint32_t)(wn * 64 + j * 16 + (lane & 7) + ((lane & 16) ? 8 : 0));
                    uint32_t off = r * 80u + kb;
                    ldsm_x4(bh + j * 4, aBh + off);
                    ldsm_x4(bl + j * 4, aBl + off);
                }
            }
#pragma unroll
            for (int i = 0; i < 2; i++) {
#pragma unroll
                for (int j = 0; j < 8; j++) {
                    int bi = (j >> 1) * 4 + (j & 1) * 2;
                    mma16816(d[i][j], ah[i], bh + bi);
                    mma16816(d[i][j], ah[i], bl + bi);
                }
            }
        }

        if (c + 1 < NC)
            storeChunk(c + 1, sbase + (uint32_t)((c + 1) & 1) * STAGE_BYTES);
        __syncthreads();
    }

    // ---- epilogue ----
    float* Cbase = (MODE == 0) ? g_node : (MODE == 1) ? g_es : Cout;
#pragma unroll
    for (int i = 0; i < 2; i++) {
        int r0 = blockRow + wm * 32 + i * 16 + (lane >> 2);
        int r1 = r0 + 8;
        bool v0 = r0 < N_NODES, v1 = r1 < N_NODES;
        float s0 = 1.f, s1 = 1.f;
        if (MODE == 1) {
            s0 = v0 ? g_deg[r0] : 0.f;
            s1 = v1 ? g_deg[r1] : 0.f;
        }
        float* c0 = Cbase + (size_t)r0 * D;
        float* c1 = Cbase + (size_t)r1 * D;
#pragma unroll
        for (int j = 0; j < 8; j++) {
            int col = wn * 64 + j * 8 + (lane & 3) * 2;
            float b0 = bias[col], b1 = bias[col + 1];
            if (v0) {
                float2 o = make_float2(d[i][j][0] + s0 * b0, d[i][j][1] + s0 * b1);
                *(float2*)(c0 + col) = o;
            }
            if (v1) {
                float2 o = make_float2(d[i][j][2] + s1 * b0, d[i][j][3] + s1 * b1);
                *(float2*)(c1 + col) = o;
            }
        }
    }
}

// ---------------------------------------------------------------------------
extern "C" void kernel_launch(void* const* d_in, const int* in_sizes, int n_in,
                              void* d_out, int out_size) {
    const float* x  = (const float*)d_in[0];
    const int*   ei = (const int*)d_in[1];
    const float* Wn = (const float*)d_in[2];
    const float* bn = (const float*)d_in[3];
    const float* We = (const float*)d_in[4];
    const float* be = (const float*)d_in[5];
    const float* Wu = (const float*)d_in[6];
    const float* bu = (const float*)d_in[7];
    float* out = (float*)d_out;
    (void)in_sizes; (void)n_in; (void)out_size;

    static bool attr_done = false;
    if (!attr_done) {
        cudaFuncSetAttribute(mma_gemm<0, 128>, cudaFuncAttributeMaxDynamicSharedMemorySize, SMEM_BYTES);
        cudaFuncSetAttribute(mma_gemm<1, 256>, cudaFuncAttributeMaxDynamicSharedMemorySize, SMEM_BYTES);
        cudaFuncSetAttribute(mma_gemm<2, 384>, cudaFuncAttributeMaxDynamicSharedMemorySize, SMEM_BYTES);
        attr_done = true;
    }

    const int egrid = (E_EDGES + 255) / 256;

    // CSR build (independent of GEMM-1; deg needed before GEMM-2)
    zero_cnt_kernel<<<(N_NODES + 255) / 256, 256>>>();
    prep_weights<<<(3 * D * D + 255) / 256, 256>>>(Wn, We, Wu);
    count_kernel<<<egrid, 256>>>(ei);
    scan1_kernel<<<NSCB, SCB>>>();
    scan2_kernel<<<1, 32>>>();
    scan3_kernel<<<NSCB, SCB>>>();
    fill_kernel<<<egrid, 256>>>(ei);

    // 1. node = x @ Wn^T + bn
    mma_gemm<0, 128><<<N_TILES, 256, SMEM_BYTES>>>(x, bn, nullptr);

    // 2. nbr_sum via CSR gather (warp per node)
    gather_kernel<<<(N_NODES * 32 + 255) / 256, 256>>>();

    // 3. edge_sum = [deg*node | nbr] @ We^T + deg*be
    mma_gemm<1, 256><<<N_TILES, 256, SMEM_BYTES>>>(nullptr, be, nullptr);

    // 4. out = gelu([node | nbr | edge_sum]) @ Wu^T + bu
    mma_gemm<2, 384><<<N_TILES, 256, SMEM_BYTES>>>(nullptr, bu, out);
}

// round 16
// speedup vs baseline: 1.4576x; 1.0486x over previous
#include <cuda_runtime.h>
#include <cuda_fp16.h>
#include <cstdint>

#define N_NODES 50000
#define D 128
#define E_EDGES 800000
#define M_TILE 128
#define N_TILES ((N_NODES + M_TILE - 1) / M_TILE)   // 391
#define STAGE_BYTES 30720  // A(10240) + Bh(10240) + Bl(10240)
#define ES_STRIDE 272      // bytes per es row (128 fp16 + 16B pad, 16B-aligned)
#define SMEM_GEMM (2 * STAGE_BYTES)
#define SMEM_FUSED (2 * STAGE_BYTES + M_TILE * ES_STRIDE)   // 96256
#define SCB 1024
#define NSCB ((N_NODES + SCB - 1) / SCB)            // 49

// ---------------- scratch globals (allocation forbidden) -------------------
__device__ __align__(16) __half g_nodeh[N_NODES * D];   // node (fp16)
__device__ __align__(16) float  g_nbr  [N_NODES * D];   // nbr_sum (fp32)
__device__ __align__(16) float  g_deg  [N_NODES];
__device__ int g_rowcnt [N_NODES];
__device__ int g_rowfill[N_NODES];
__device__ int g_rowptr [N_NODES + 1];
__device__ int g_csr    [E_EDGES];
__device__ int g_bsum   [NSCB];
__device__ __align__(16) __half g_Wn_h[D *     D];
__device__ __align__(16) __half g_Wn_l[D *     D];
__device__ __align__(16) __half g_We_h[D * 2 * D];
__device__ __align__(16) __half g_We_l[D * 2 * D];
__device__ __align__(16) __half g_Wu_h[D * 3 * D];
__device__ __align__(16) __half g_Wu_l[D * 3 * D];

// ---------------- helpers ---------------------------------------------------
__device__ __forceinline__ uint32_t smem_u32(const void* p) {
    uint32_t a;
    asm("{ .reg .u64 t; cvta.to.shared.u64 t, %1; cvt.u32.u64 %0, t; }"
        : "=r"(a) : "l"(p));
    return a;
}
__device__ __forceinline__ void sts128(uint32_t addr, uint4 v) {
    asm volatile("st.shared.v4.b32 [%0], {%1, %2, %3, %4};"
                 :: "r"(addr), "r"(v.x), "r"(v.y), "r"(v.z), "r"(v.w) : "memory");
}
__device__ __forceinline__ void sts32(uint32_t addr, uint32_t v) {
    asm volatile("st.shared.b32 [%0], %1;" :: "r"(addr), "r"(v) : "memory");
}
__device__ __forceinline__ uint4 lds128(uint32_t addr) {
    uint4 v;
    asm volatile("ld.shared.v4.b32 {%0, %1, %2, %3}, [%4];"
                 : "=r"(v.x), "=r"(v.y), "=r"(v.z), "=r"(v.w) : "r"(addr));
    return v;
}
__device__ __forceinline__ void ldsm_x4(uint32_t* r, uint32_t addr) {
    asm volatile("ldmatrix.sync.aligned.m8n8.x4.shared.b16 {%0, %1, %2, %3}, [%4];"
                 : "=r"(r[0]), "=r"(r[1]), "=r"(r[2]), "=r"(r[3]) : "r"(addr));
}
__device__ __forceinline__ void mma16816(float* d, const uint32_t* a, const uint32_t* b) {
    asm volatile(
        "mma.sync.aligned.m16n8k16.row.col.f32.f16.f16.f32 "
        "{%0, %1, %2, %3}, {%4, %5, %6, %7}, {%8, %9}, {%0, %1, %2, %3};"
        : "+f"(d[0]), "+f"(d[1]), "+f"(d[2]), "+f"(d[3])
        : "r"(a[0]), "r"(a[1]), "r"(a[2]), "r"(a[3]), "r"(b[0]), "r"(b[1]));
}
__device__ __forceinline__ uint32_t pack_h2(float a, float b) {
    __half2 h = __floats2half2_rn(a, b);
    return *reinterpret_cast<uint32_t*>(&h);
}
__device__ __forceinline__ float gelu_exact(float u) {
    return 0.5f * u * (1.0f + erff(u * 0.70710678118654752f));
}
// 8 fp16 in a uint4 -> op -> repack
__device__ __forceinline__ uint4 proc8h(uint4 u, float scale, bool doGelu) {
    uint4 r;
    const uint32_t* s = &u.x;
    uint32_t* o = &r.x;
#pragma unroll
    for (int k = 0; k < 4; k++) {
        __half2 h = *reinterpret_cast<const __half2*>(&s[k]);
        float2 f = __half22float2(h);
        f.x *= scale; f.y *= scale;
        if (doGelu) { f.x = gelu_exact(f.x); f.y = gelu_exact(f.y); }
        o[k] = pack_h2(f.x, f.y);
    }
    return r;
}

// ---------------------------------------------------------------------------
__global__ void zero_cnt_kernel() {
    int i = blockIdx.x * blockDim.x + threadIdx.x;
    if (i < N_NODES) { g_rowcnt[i] = 0; g_rowfill[i] = 0; }
}

// Split weights to fp16 hi/lo; layout stays [n][K] (K-major = mma ".col" B).
__global__ void prep_weights(const float* __restrict__ Wn,
                             const float* __restrict__ We,
                             const float* __restrict__ Wu) {
    int i = blockIdx.x * blockDim.x + threadIdx.x;
    if (i < D * D) {
        float w = Wn[i];
        __half h = __float2half_rn(w);
        g_Wn_h[i] = h; g_Wn_l[i] = __float2half_rn(w - __half2float(h));
    }
    if (i < 2 * D * D) {
        float w = We[i];
        __half h = __float2half_rn(w);
        g_We_h[i] = h; g_We_l[i] = __float2half_rn(w - __half2float(h));
    }
    if (i < 3 * D * D) {
        float w = Wu[i];
        __half h = __float2half_rn(w);
        g_Wu_h[i] = h; g_Wu_l[i] = __float2half_rn(w - __half2float(h));
    }
}

// ---------------- CSR build --------------------------------------------------
__global__ void count_kernel(const int* __restrict__ ei) {
    int e = blockIdx.x * blockDim.x + threadIdx.x;
    if (e < E_EDGES) atomicAdd(&g_rowcnt[ei[e]], 1);
}

__global__ void __launch_bounds__(SCB) scan1_kernel() {
    __shared__ int s[SCB];
    int t = threadIdx.x;
    int i = blockIdx.x * SCB + t;
    int c = (i < N_NODES) ? g_rowcnt[i] : 0;
    s[t] = c;
    __syncthreads();
#pragma unroll
    for (int off = 1; off < SCB; off <<= 1) {
        int v = (t >= off) ? s[t - off] : 0;
        __syncthreads();
        s[t] += v;
        __syncthreads();
    }
    if (i < N_NODES) {
        g_rowptr[i] = s[t] - c;
        g_deg[i] = (float)c;
    }
    if (t == SCB - 1) g_bsum[blockIdx.x] = s[t];
}

__global__ void scan2_kernel() {
    if (threadIdx.x == 0) {
        int run = 0;
        for (int b = 0; b < NSCB; b++) {
            int v = g_bsum[b];
            g_bsum[b] = run;
            run += v;
        }
        g_rowptr[N_NODES] = run;
    }
}

__global__ void __launch_bounds__(SCB) scan3_kernel() {
    int i = blockIdx.x * SCB + threadIdx.x;
    if (i < N_NODES && blockIdx.x > 0) g_rowptr[i] += g_bsum[blockIdx.x];
}

__global__ void fill_kernel(const int* __restrict__ ei) {
    int e = blockIdx.x * blockDim.x + threadIdx.x;
    if (e >= E_EDGES) return;
    int s = ei[e];
    int pos = atomicAdd(&g_rowfill[s], 1);
    g_csr[g_rowptr[s] + pos] = ei[E_EDGES + e];
}

// Gather (fp16 node, fp32 accum): one warp per node, lane owns 4 columns.
__global__ void __launch_bounds__(256) gather_kernel() {
    int node = (blockIdx.x * blockDim.x + threadIdx.x) >> 5;
    if (node >= N_NODES) return;
    int lane = threadIdx.x & 31;
    int i   = g_rowptr[node];
    int end = g_rowptr[node + 1];
    float4 acc = make_float4(0.f, 0.f, 0.f, 0.f);
    for (; i + 4 <= end; i += 4) {
        int d0 = g_csr[i], d1 = g_csr[i + 1], d2 = g_csr[i + 2], d3 = g_csr[i + 3];
        uint2 u0 = ((const uint2*)(g_nodeh + (size_t)d0 * D))[lane];
        uint2 u1 = ((const uint2*)(g_nodeh + (size_t)d1 * D))[lane];
        uint2 u2 = ((const uint2*)(g_nodeh + (size_t)d2 * D))[lane];
        uint2 u3 = ((const uint2*)(g_nodeh + (size_t)d3 * D))[lane];
#pragma unroll
        for (int q = 0; q < 4; q++) {
            uint2 u = (q == 0) ? u0 : (q == 1) ? u1 : (q == 2) ? u2 : u3;
            float2 a = __half22float2(*reinterpret_cast<const __half2*>(&u.x));
            float2 b = __half22float2(*reinterpret_cast<const __half2*>(&u.y));
            acc.x += a.x; acc.y += a.y; acc.z += b.x; acc.w += b.y;
        }
    }
    for (; i < end; i++) {
        uint2 u = ((const uint2*)(g_nodeh + (size_t)g_csr[i] * D))[lane];
        float2 a = __half22float2(*reinterpret_cast<const __half2*>(&u.x));
        float2 b = __half22float2(*reinterpret_cast<const __half2*>(&u.y));
        acc.x += a.x; acc.y += a.y; acc.z += b.x; acc.w += b.y;
    }
    ((float4*)(g_nbr + (size_t)node * D))[lane] = acc;
}

// ---------------------------------------------------------------------------
// GEMM-0: node = x @ Wn^T + bn, output fp16 (g_nodeh).
// CTA 128x128, 256 threads, 8 warps (4x2), BK=32, double-buffered.
__global__ void __launch_bounds__(256) mma_gemm0(const float* __restrict__ A0,
                                                 const float* __restrict__ bias) {
    extern __shared__ __align__(16) char dynsmem[];
    const uint32_t sbase = smem_u32(dynsmem);

    const int tid  = threadIdx.x;
    const int lane = tid & 31;
    const int wid  = tid >> 5;
    const int wm   = wid >> 1;
    const int wn   = wid & 1;
    const int blockRow = blockIdx.x * M_TILE;
    const int ldRow = tid >> 1;
    const int half  = tid & 1;
    const int mA    = blockRow + ldRow;
    const bool mvA  = (mA < N_NODES);

    float d[2][8][4];
#pragma unroll
    for (int i = 0; i < 2; i++)
#pragma unroll
        for (int j = 0; j < 8; j++)
#pragma unroll
            for (int q = 0; q < 4; q++) d[i][j][q] = 0.f;

    float4 aReg[4];
    uint4  bRegH[2], bRegL[2];

    auto loadChunk = [&](int c) {
        const float4* p4 = (const float4*)(A0 + (size_t)mA * D + c * 32 + half * 16);
        if (mvA) {
#pragma unroll
            for (int q = 0; q < 4; q++) aReg[q] = p4[q];
        } else {
            float4 z = make_float4(0.f, 0.f, 0.f, 0.f);
#pragma unroll
            for (int q = 0; q < 4; q++) aReg[q] = z;
        }
        const uint4* ph = (const uint4*)(g_Wn_h + (size_t)ldRow * D + c * 32 + half * 16);
        const uint4* pl = (const uint4*)(g_Wn_l + (size_t)ldRow * D + c * 32 + half * 16);
        bRegH[0] = ph[0]; bRegH[1] = ph[1];
        bRegL[0] = pl[0]; bRegL[1] = pl[1];
    };
    auto storeChunk = [&](uint32_t stage) {
        uint4 H[2];
#pragma unroll
        for (int q = 0; q < 2; q++) {
            float4 fa = aReg[2 * q], fb = aReg[2 * q + 1];
            H[q].x = pack_h2(fa.x, fa.y);
            H[q].y = pack_h2(fa.z, fa.w);
            H[q].z = pack_h2(fb.x, fb.y);
            H[q].w = pack_h2(fb.z, fb.w);
        }
        uint32_t off = (uint32_t)ldRow * 80u + half * 32u;
        sts128(stage + off,               H[0]);
        sts128(stage + off + 16,          H[1]);
        sts128(stage + 10240 + off,       bRegH[0]);
        sts128(stage + 10240 + off + 16,  bRegH[1]);
        sts128(stage + 20480 + off,       bRegL[0]);
        sts128(stage + 20480 + off + 16,  bRegL[1]);
    };
    auto consume = [&](uint32_t cur) {
#pragma unroll
        for (int ks = 0; ks < 2; ks++) {
            uint32_t ah[2][4];
            uint32_t kbA = (uint32_t)(ks * 16 + ((lane >> 4) << 3)) * 2u;
#pragma unroll
            for (int i = 0; i < 2; i++) {
                uint32_t r = (uint32_t)(wm * 32 + i * 16 + (lane & 15));
                ldsm_x4(ah[i], cur + r * 80u + kbA);
            }
            uint32_t bh[16], bl[16];
            uint32_t kbB = (uint32_t)(ks * 16 + (lane & 8)) * 2u;
#pragma unroll
            for (int j = 0; j < 4; j++) {
                uint32_t r = (uint32_t)(wn * 64 + j * 16 + (lane & 7) + ((lane & 16) ? 8 : 0));
                uint32_t off = r * 80u + kbB;
                ldsm_x4(bh + j * 4, cur + 10240 + off);
                ldsm_x4(bl + j * 4, cur + 20480 + off);
            }
#pragma unroll
            for (int i = 0; i < 2; i++)
#pragma unroll
                for (int j = 0; j < 8; j++) {
                    int bi = (j >> 1) * 4 + (j & 1) * 2;
                    mma16816(d[i][j], ah[i], bh + bi);
                    mma16816(d[i][j], ah[i], bl + bi);
                }
        }
    };

    loadChunk(0);
    storeChunk(sbase);
    __syncthreads();
    for (int c = 0; c < 4; c++) {
        uint32_t cur = sbase + (uint32_t)(c & 1) * STAGE_BYTES;
        if (c + 1 < 4) loadChunk(c + 1);
        consume(cur);
        if (c + 1 < 4) storeChunk(sbase + (uint32_t)((c + 1) & 1) * STAGE_BYTES);
        __syncthreads();
    }

    // epilogue -> fp16 g_nodeh
#pragma unroll
    for (int i = 0; i < 2; i++) {
        int r0 = blockRow + wm * 32 + i * 16 + (lane >> 2);
        int r1 = r0 + 8;
#pragma unroll
        for (int j = 0; j < 8; j++) {
            int col = wn * 64 + j * 8 + (lane & 3) * 2;
            float b0 = bias[col], b1 = bias[col + 1];
            if (r0 < N_NODES)
                *(uint32_t*)(g_nodeh + (size_t)r0 * D + col) = pack_h2(d[i][j][0] + b0, d[i][j][1] + b1);
            if (r1 < N_NODES)
                *(uint32_t*)(g_nodeh + (size_t)r1 * D + col) = pack_h2(d[i][j][2] + b0, d[i][j][3] + b1);
        }
    }
}

// ---------------------------------------------------------------------------
// Fused GEMM-1 + GEMM-2:
//   Phase A: es = [deg*node | nbr] @ We^T + deg*be    -> smem es tile (fp16)
//   Phase B: out = gelu([node | nbr | es]) @ Wu^T + bu
__global__ void __launch_bounds__(256) mma_fused(const float* __restrict__ be,
                                                 const float* __restrict__ bu,
                                                 float* __restrict__ Cout) {
    extern __shared__ __align__(16) char dynsmem[];
    const uint32_t sbase = smem_u32(dynsmem);
    const uint32_t esb   = sbase + 2 * STAGE_BYTES;

    const int tid  = threadIdx.x;
    const int lane = tid & 31;
    const int wid  = tid >> 5;
    const int wm   = wid >> 1;
    const int wn   = wid & 1;
    const int blockRow = blockIdx.x * M_TILE;
    const int ldRow = tid >> 1;
    const int half  = tid & 1;
    const int mA    = blockRow + ldRow;
    const bool mvA  = (mA < N_NODES);
    const float degA = mvA ? g_deg[mA] : 0.f;

    float d[2][8][4];

    uint4  aH[2];        // fp16 A source (node / es)
    float4 aF[4];        // fp32 A source (nbr)
    uint4  bRegH[2], bRegL[2];

    auto loadB = [&](const __half* WH, const __half* WL, int K, int c) {
        const uint4* ph = (const uint4*)(WH + (size_t)ldRow * K + c * 32 + half * 16);
        const uint4* pl = (const uint4*)(WL + (size_t)ldRow * K + c * 32 + half * 16);
        bRegH[0] = ph[0]; bRegH[1] = ph[1];
        bRegL[0] = pl[0]; bRegL[1] = pl[1];
    };
    auto loadNode16 = [&](int c) {     // 16 fp16 from g_nodeh
        const uint4* p = (const uint4*)(g_nodeh + (size_t)mA * D + c * 32 + half * 16);
        if (mvA) { aH[0] = p[0]; aH[1] = p[1]; }
        else { aH[0] = make_uint4(0,0,0,0); aH[1] = make_uint4(0,0,0,0); }
    };
    auto loadNbr32 = [&](int c) {      // 16 fp32 from g_nbr
        const float4* p = (const float4*)(g_nbr + (size_t)mA * D + c * 32 + half * 16);
        if (mvA) {
#pragma unroll
            for (int q = 0; q < 4; q++) aF[q] = p[q];
        } else {
            float4 z = make_float4(0.f, 0.f, 0.f, 0.f);
#pragma unroll
            for (int q = 0; q < 4; q++) aF[q] = z;
        }
    };
    auto storeStageA = [&](uint32_t stage, uint4 H0, uint4 H1) {
        uint32_t off = (uint32_t)ldRow * 80u + half * 32u;
        sts128(stage + off,              H0);
        sts128(stage + off + 16,         H1);
        sts128(stage + 10240 + off,      bRegH[0]);
        sts128(stage + 10240 + off + 16, bRegH[1]);
        sts128(stage + 20480 + off,      bRegL[0]);
        sts128(stage + 20480 + off + 16, bRegL[1]);
    };
    auto packF = [&](float4 fa, float4 fb, bool doGelu) -> uint4 {
        if (doGelu) {
            fa.x = gelu_exact(fa.x); fa.y = gelu_exact(fa.y);
            fa.z = gelu_exact(fa.z); fa.w = gelu_exact(fa.w);
            fb.x = gelu_exact(fb.x); fb.y = gelu_exact(fb.y);
            fb.z = gelu_exact(fb.z); fb.w = gelu_exact(fb.w);
        }
        uint4 H;
        H.x = pack_h2(fa.x, fa.y); H.y = pack_h2(fa.z, fa.w);
        H.z = pack_h2(fb.x, fb.y); H.w = pack_h2(fb.z, fb.w);
        return H;
    };
    auto consume = [&](uint32_t cur) {
#pragma unroll
        for (int ks = 0; ks < 2; ks++) {
            uint32_t ah[2][4];
            uint32_t kbA = (uint32_t)(ks * 16 + ((lane >> 4) << 3)) * 2u;
#pragma unroll
            for (int i = 0; i < 2; i++) {
                uint32_t r = (uint32_t)(wm * 32 + i * 16 + (lane & 15));
                ldsm_x4(ah[i], cur + r * 80u + kbA);
            }
            uint32_t bh[16], bl[16];
            uint32_t kbB = (uint32_t)(ks * 16 + (lane & 8)) * 2u;
#pragma unroll
            for (int j = 0; j < 4; j++) {
                uint32_t r = (uint32_t)(wn * 64 + j * 16 + (lane & 7) + ((lane & 16) ? 8 : 0));
                uint32_t off = r * 80u + kbB;
                ldsm_x4(bh + j * 4, cur + 10240 + off);
                ldsm_x4(bl + j * 4, cur + 20480 + off);
            }
#pragma unroll
            for (int i = 0; i < 2; i++)
#pragma unroll
                for (int j = 0; j < 8; j++) {
                    int bi = (j >> 1) * 4 + (j & 1) * 2;
                    mma16816(d[i][j], ah[i], bh + bi);
                    mma16816(d[i][j], ah[i], bl + bi);
                }
        }
    };

    // ================= PHASE A: es = [deg*node | nbr] @ We^T ================
#pragma unroll
    for (int i = 0; i < 2; i++)
#pragma unroll
        for (int j = 0; j < 8; j++)
#pragma unroll
            for (int q = 0; q < 4; q++) d[i][j][q] = 0.f;

    auto loadA_A = [&](int c) {
        if (c < 4) loadNode16(c); else loadNbr32(c - 4);
        loadB(g_We_h, g_We_l, 2 * D, c);
    };
    auto storeA_A = [&](int c, uint32_t stage) {
        uint4 H0, H1;
        if (c < 4) {                       // deg * node (fp16 src)
            H0 = proc8h(aH[0], degA, false);
            H1 = proc8h(aH[1], degA, false);
        } else {                           // nbr (fp32 src)
            H0 = packF(aF[0], aF[1], false);
            H1 = packF(aF[2], aF[3], false);
        }
        storeStageA(stage, H0, H1);
    };

    loadA_A(0);
    storeA_A(0, sbase);
    __syncthreads();
    for (int c = 0; c < 8; c++) {
        uint32_t cur = sbase + (uint32_t)(c & 1) * STAGE_BYTES;
        if (c + 1 < 8) loadA_A(c + 1);
        consume(cur);
        if (c + 1 < 8) storeA_A(c + 1, sbase + (uint32_t)((c + 1) & 1) * STAGE_BYTES);
        __syncthreads();
    }

    // es epilogue -> smem fp16 tile (rows CTA-local)
#pragma unroll
    for (int i = 0; i < 2; i++) {
        int lr0 = wm * 32 + i * 16 + (lane >> 2);
        int lr1 = lr0 + 8;
        int gr0 = blockRow + lr0, gr1 = blockRow + lr1;
        float s0 = (gr0 < N_NODES) ? g_deg[gr0] : 0.f;
        float s1 = (gr1 < N_NODES) ? g_deg[gr1] : 0.f;
#pragma unroll
        for (int j = 0; j < 8; j++) {
            int col = wn * 64 + j * 8 + (lane & 3) * 2;
            float b0 = be[col], b1 = be[col + 1];
            sts32(esb + (uint32_t)lr0 * ES_STRIDE + col * 2,
                  pack_h2(d[i][j][0] + s0 * b0, d[i][j][1] + s0 * b1));
            sts32(esb + (uint32_t)lr1 * ES_STRIDE + col * 2,
                  pack_h2(d[i][j][2] + s1 * b0, d[i][j][3] + s1 * b1));
        }
    }
    __syncthreads();

    // ================= PHASE B: out = gelu([node|nbr|es]) @ Wu^T ============
#pragma unroll
    for (int i = 0; i < 2; i++)
#pragma unroll
        for (int j = 0; j < 8; j++)
#pragma unroll
            for (int q = 0; q < 4; q++) d[i][j][q] = 0.f;

    auto loadA_B = [&](int c) {
        if (c < 4) loadNode16(c);
        else if (c < 8) loadNbr32(c - 4);
        else {  // es from smem
            uint32_t a = esb + (uint32_t)ldRow * ES_STRIDE + (uint32_t)((c - 8) * 64 + half * 32);
            aH[0] = lds128(a);
            aH[1] = lds128(a + 16);
        }
        loadB(g_Wu_h, g_Wu_l, 3 * D, c);
    };
    auto storeA_B = [&](int c, uint32_t stage) {
        uint4 H0, H1;
        if (c < 4 || c >= 8) {             // fp16 src (node or es): gelu
            H0 = proc8h(aH[0], 1.f, true);
            H1 = proc8h(aH[1], 1.f, true);
        } else {                           // nbr fp32: gelu
            H0 = packF(aF[0], aF[1], true);
            H1 = packF(aF[2], aF[3], true);
        }
        storeStageA(stage, H0, H1);
    };

    loadA_B(0);
    storeA_B(0, sbase);
    __syncthreads();
    for (int c = 0; c < 12; c++) {
        uint32_t cur = sbase + (uint32_t)(c & 1) * STAGE_BYTES;
        if (c + 1 < 12) loadA_B(c + 1);
        consume(cur);
        if (c + 1 < 12) storeA_B(c + 1, sbase + (uint32_t)((c + 1) & 1) * STAGE_BYTES);
        __syncthreads();
    }

    // final epilogue -> out (fp32)
#pragma unroll
    for (int i = 0; i < 2; i++) {
        int r0 = blockRow + wm * 32 + i * 16 + (lane >> 2);
        int r1 = r0 + 8;
#pragma unroll
        for (int j = 0; j < 8; j++) {
            int col = wn * 64 + j * 8 + (lane & 3) * 2;
            float b0 = bu[col], b1 = bu[col + 1];
            if (r0 < N_NODES) {
                float2 o = make_float2(d[i][j][0] + b0, d[i][j][1] + b1);
                *(float2*)(Cout + (size_t)r0 * D + col) = o;
            }
            if (r1 < N_NODES) {
                float2 o = make_float2(d[i][j][2] + b0, d[i][j][3] + b1);
                *(float2*)(Cout + (size_t)r1 * D + col) = o;
            }
        }
    }
}

// ---------------------------------------------------------------------------
extern "C" void kernel_launch(void* const* d_in, const int* in_sizes, int n_in,
                              void* d_out, int out_size) {
    const float* x  = (const float*)d_in[0];
    const int*   ei = (const int*)d_in[1];
    const float* Wn = (const float*)d_in[2];
    const float* bn = (const float*)d_in[3];
    const float* We = (const float*)d_in[4];
    const float* be = (const float*)d_in[5];
    const float* Wu = (const float*)d_in[6];
    const float* bu = (const float*)d_in[7];
    float* out = (float*)d_out;
    (void)in_sizes; (void)n_in; (void)out_size; (void)We; (void)Wu;

    static bool attr_done = false;
    if (!attr_done) {
        cudaFuncSetAttribute(mma_gemm0, cudaFuncAttributeMaxDynamicSharedMemorySize, SMEM_GEMM);
        cudaFuncSetAttribute(mma_fused, cudaFuncAttributeMaxDynamicSharedMemorySize, SMEM_FUSED);
        attr_done = true;
    }

    const int egrid = (E_EDGES + 255) / 256;

    // CSR build
    zero_cnt_kernel<<<(N_NODES + 255) / 256, 256>>>();
    prep_weights<<<(3 * D * D + 255) / 256, 256>>>(Wn, We, Wu);
    count_kernel<<<egrid, 256>>>(ei);
    scan1_kernel<<<NSCB, SCB>>>();
    scan2_kernel<<<1, 32>>>();
    scan3_kernel<<<NSCB, SCB>>>();
    fill_kernel<<<egrid, 256>>>(ei);

    // 1. node = x @ Wn^T + bn  (fp16 output)
    mma_gemm0<<<N_TILES, 256, SMEM_GEMM>>>(x, bn);

    // 2. nbr_sum via CSR gather (warp per node, fp16 reads)
    gather_kernel<<<(N_NODES * 32 + 255) / 256, 256>>>();

    // 3+4. fused: es (smem) then out = gelu([node|nbr|es]) @ Wu^T + bu
    mma_fused<<<N_TILES, 256, SMEM_FUSED>>>(be, bu, out);
}